// round 11
// baseline (speedup 1.0000x reference)
#include <cuda_runtime.h>
#include <cstdint>

// SpottingLoss: greedy bipartite matching + YOLO-style loss.
// B=2048 batches, N=64 slots, F=19 features. One warp per batch, 4 independent
// warps per 128-thread block (no block barriers anywhere).
// R10: ZERO scattered LDGs. Both tiles arrive via coalesced 16B cp.async
//      (19 LDGSTS per lane, no register scoreboard); alpha/x/pm/matching/
//      epilogue are all LDS. Eliminates the ~8x sector amplification and
//      ~3x request count of the scattered-load versions (R5/R7/R9 all ~15us).
// Kept: phase-1 elimination, pm-poison free-set, 8x8 tree argmax,
//       lane-compacted proposals (ballot+__fns), fused grid reduction.

#define N_ 64
#define F_ 19
#define TILE_FLOATS (N_ * F_)             // 1216 floats = 4864 B per tile
#define TILE_CHUNKS (TILE_FLOATS / 4)     // 304 x 16B
#define BOTH_CHUNKS (2 * TILE_CHUNKS)     // 608 = 19 * 32 exactly
#define WPB 4                             // independent warps (batches) / block
#define LAMBDA_COORD 5.0f
#define LAMBDA_NOOBJ 0.5f
#define FULLM 0xFFFFFFFFu

// Grid-reduction scratch. Zero-initialized at module load; the LAST warp of
// every launch resets both, so each graph replay starts clean.
__device__ float    g_acc   = 0.0f;
__device__ unsigned g_count = 0u;

// Column-acceptance key: (value bits << 32) | ~row. Proposal values are > 0,
// so float bits are monotone; larger key = larger value, then lower row index
// — exactly the reference's argmax-over-rows tie-breaking.
__device__ __forceinline__ unsigned long long mk_key(float v, int row) {
    return ((unsigned long long)__float_as_uint(v) << 32) |
           (unsigned long long)(FULLM - (unsigned)row);
}

__device__ __forceinline__ void cp_async16(uint32_t smem_dst, const void* gsrc) {
    asm volatile("cp.async.cg.shared.global [%0], [%1], 16;"
                 :: "r"(smem_dst), "l"(gsrc) : "memory");
}

struct __align__(16) WarpSmem {
    float yt[TILE_FLOATS];    // y_true tile  (yt+yp contiguous: one dst range)
    float yp[TILE_FLOATS];    // y_pred tile
    float pm[N_];             // free-set: p while free, 3.0f poison once taken
    unsigned long long colkey[N_];
    int   perm[N_];
};

__global__ __launch_bounds__(32 * WPB) void spotting_loss_kernel(
    const float* __restrict__ y_true,
    const float* __restrict__ y_pred,
    float* __restrict__ out,
    int batches)
{
    __shared__ WarpSmem ws[WPB];

    const int w    = threadIdx.x >> 5;
    const int lane = threadIdx.x & 31;
    const int b    = blockIdx.x * WPB + w;

    WarpSmem& s = ws[w];
    float term = 0.0f;

    if (b < batches) {
        const float* gt = y_true + (size_t)b * TILE_FLOATS;
        const float* gp = y_pred + (size_t)b * TILE_FLOATS;

        // ---- Coalesced staging: 608 16B chunks = exactly 19 LDGSTS/lane ----
        {
            uint32_t dst = (uint32_t)__cvta_generic_to_shared(s.yt);
            const char* g0 = (const char*)gt;
            const char* g1 = (const char*)gp;
#pragma unroll
            for (int k = 0; k < BOTH_CHUNKS / 32; ++k) {      // 19
                int idx = lane + k * 32;
                const char* src = (idx < TILE_CHUNKS)
                                ? g0 + idx * 16
                                : g1 + (idx - TILE_CHUNKS) * 16;
                cp_async16(dst + idx * 16, src);
            }
            asm volatile("cp.async.commit_group;" ::: "memory");
        }
        s.colkey[lane]      = 0ull;   // init once; never reset (round invariant)
        s.colkey[lane + 32] = 0ull;
        asm volatile("cp.async.wait_group 0;" ::: "memory");
        __syncwarp();

        const int r0 = lane, r1 = lane + 32;
        // Stride 19 is coprime with 32 banks -> these LDS are conflict-free.
        const float a0 = s.yt[r0 * F_ + 0];     // exactly 0.0f or 1.0f
        const float x0 = s.yt[r0 * F_ + 1];
        const float a1 = s.yt[r1 * F_ + 0];
        const float x1 = s.yt[r1 * F_ + 1];
        s.pm[r0] = s.yp[r0 * F_ + 1];
        s.pm[r1] = s.yp[r1 * F_ + 1];
        __syncwarp();

        // Active mask over 64 rows (alpha==1 only; phase 1 is eliminated).
        unsigned bl0 = __ballot_sync(FULLM, a0 > 0.5f);
        unsigned bl1 = __ballot_sync(FULLM, a1 > 0.5f);
        unsigned long long act = (unsigned long long)bl0 |
                                 ((unsigned long long)bl1 << 32);

        // Invariant: every column proposed in a round is matched in that
        // round, so colkey entries are never reused and pm poison is the
        // only free-set representation.
        while (act) {
            const int      cnt = __popcll(act);
            const unsigned lo  = (unsigned)act;
            const unsigned hi  = (unsigned)(act >> 32);
            const int      plo = __popc(lo);

            int pr[2], pj[2];
            pr[0] = pr[1] = -1;
            unsigned long long kill = 0;

            // Proposal: lane takes the (base+lane)-th active row (ascending).
            for (int base = 0; base < cnt; base += 32) {
                const int t = base >> 5;
                const int i = base + lane;
                if (i < cnt) {
                    const int r = (i < plo)
                                ? (int)__fns(lo, 0, i + 1)
                                : 32 + (int)__fns(hi, 0, i - plo + 1);
                    const float xr = s.yt[r * F_ + 1];   // LDS, <=2-way conflict

                    // 8x8 two-level argmax, strict > = first-index ties (JAX).
                    float cv[8]; int cj[8];
#pragma unroll
                    for (int c = 0; c < 8; ++c) {
                        float bv = -10.0f; int bi = c * 8;
#pragma unroll
                        for (int kk = 0; kk < 8; ++kk) {
                            int j = c * 8 + kk;
                            float v = 1.0f - fabsf(xr - s.pm[j]);
                            if (v > bv) { bv = v; bi = j; }
                        }
                        cv[c] = bv; cj[c] = bi;
                    }
                    float bv = cv[0]; int bj = cj[0];
#pragma unroll
                    for (int c = 1; c < 8; ++c)
                        if (cv[c] > bv) { bv = cv[c]; bj = cj[c]; }

                    atomicMax(&s.colkey[bj], mk_key(bv, r));
                    pr[t] = r; pj[t] = bj;
                }
            }
            __syncwarp();                  // proposals visible warp-wide

            // Acceptance: max-key proposer of each proposed column wins,
            // poisons it, records perm, retires its row.
#pragma unroll
            for (int t = 0; t < 2; ++t) {
                const int r = pr[t];
                if (r >= 0) {
                    const int bj = pj[t];
                    unsigned wr = FULLM -
                        (unsigned)(s.colkey[bj] & 0xFFFFFFFFull);
                    if (wr == (unsigned)r) {
                        s.perm[r] = bj;
                        s.pm[bj]  = 3.0f;          // poison (single writer)
                        kill |= 1ull << r;
                    }
                }
            }
            // Combine retired rows via warp reduction of `kill` (no smem mask).
#pragma unroll
            for (int o = 16; o; o >>= 1)
                kill |= __shfl_xor_sync(FULLM, kill, o);
            act &= ~kill;
            __syncwarp();                  // poison/perm visible next round
        }
        __syncwarp();

        // ---- Epilogue: pure LDS ----
        if (a0 > 0.5f) {
            const float* gtr = &s.yt[r0 * F_];
            const float* ypr = &s.yp[s.perm[r0] * F_];
            const float d0 = 1.0f - ypr[0];
            const float dx = x0 - ypr[1];
            float sq = 0.0f;
#pragma unroll
            for (int f = 2; f < F_; ++f) {
                float d = gtr[f] - ypr[f];
                sq += d * d;
            }
            term += LAMBDA_COORD * dx * dx + d0 * d0 + sq;
        }
        if (a1 > 0.5f) {
            const float* gtr = &s.yt[r1 * F_];
            const float* ypr = &s.yp[s.perm[r1] * F_];
            const float d0 = 1.0f - ypr[0];
            const float dx = x1 - ypr[1];
            float sq = 0.0f;
#pragma unroll
            for (int f = 2; f < F_; ++f) {
                float d = gtr[f] - ypr[f];
                sq += d * d;
            }
            term += LAMBDA_COORD * dx * dx + d0 * d0 + sq;
        }
        // alpha=0 contribution per COLUMN: every column not taken in phase 0
        // is assigned to exactly one alpha=0 row -> 0.5*yp[col,0]^2.
        if (s.pm[r0] != 3.0f) {
            float p = s.yp[r0 * F_ + 0];
            term += LAMBDA_NOOBJ * p * p;
        }
        if (s.pm[r1] != 3.0f) {
            float p = s.yp[r1 * F_ + 0];
            term += LAMBDA_NOOBJ * p * p;
        }
    }

    // Warp reduction, then grid reduction via device scratch. Every warp
    // participates in the ticket (even out-of-range ones) so the last-warp
    // finalize is exact.
#pragma unroll
    for (int o = 16; o; o >>= 1) term += __shfl_down_sync(FULLM, term, o);

    if (lane == 0) {
        atomicAdd(&g_acc, term);
        __threadfence();
        unsigned ticket = atomicAdd(&g_count, 1u);
        if (ticket == gridDim.x * WPB - 1) {          // last warp finalizes
            float total = atomicAdd(&g_acc, 0.0f);    // coherent read
            out[0]  = total;
            g_acc   = 0.0f;                           // reset for next replay
            g_count = 0u;
        }
    }
}

extern "C" void kernel_launch(void* const* d_in, const int* in_sizes, int n_in,
                              void* d_out, int out_size)
{
    const float* y_true = (const float*)d_in[0];
    const float* y_pred = (const float*)d_in[1];
    float* out = (float*)d_out;

    int batches = in_sizes[0] / (N_ * F_);            // 2048
    int grid = (batches + WPB - 1) / WPB;             // 512
    spotting_loss_kernel<<<grid, 32 * WPB>>>(y_true, y_pred, out, batches);
}